// round 15
// baseline (speedup 1.0000x reference)
#include <cuda_runtime.h>
#include <float.h>
#include <math.h>

#define B_ 8
#define C_ 32
#define H_ 512
#define W_ 512
#define HW_ (H_*W_)

typedef unsigned long long u64;

// Scratch (allocation-free rule: static __device__ arrays)
__device__ float g_fs[B_*C_*H_*W_];   // conv1x1 output (pre-attention)
__device__ float g_cm[B_*H_*W_];      // channel max plane
__device__ float g_ca[B_*H_*W_];      // channel mean plane

__device__ __forceinline__ float fsigmoid(float z) {
    return 1.0f / (1.0f + __expf(-z));
}

// ---- packed f32x2 helpers (sm_10x) ----
__device__ __forceinline__ u64 pack2(float lo, float hi) {
    u64 r; asm("mov.b64 %0, {%1,%2};" : "=l"(r) : "f"(lo), "f"(hi)); return r;
}
__device__ __forceinline__ u64 dup2(float v) { return pack2(v, v); }
__device__ __forceinline__ void unpack2(u64 v, float &lo, float &hi) {
    asm("mov.b64 {%0,%1}, %2;" : "=f"(lo), "=f"(hi) : "l"(v));
}
__device__ __forceinline__ void fma2acc(u64 &acc, u64 a, u64 b) {
    asm("fma.rn.f32x2 %0, %1, %2, %0;" : "+l"(acc) : "l"(a), "l"(b));
}
__device__ __forceinline__ u64 fma2(u64 a, u64 b, u64 c) {
    u64 d; asm("fma.rn.f32x2 %0, %1, %2, %3;" : "=l"(d) : "l"(a), "l"(b), "l"(c)); return d;
}
__device__ __forceinline__ void add2acc(u64 &acc, u64 b) {
    asm("add.rn.f32x2 %0, %0, %1;" : "+l"(acc) : "l"(b));
}

// 4-float-group bank swizzle: flip group bit0 when group bit3 set.
__device__ __forceinline__ int swzg(int g) { return g ^ ((g >> 3) & 1); }
__device__ __forceinline__ int swzf(int cc) {
    int g = cc >> 2;
    return ((g ^ ((g >> 3) & 1)) << 2) | (cc & 3);
}

// ---------------------------------------------------------------------------
// Kernel A (R6 form, occupancy 3): per 2x2 patch, 2 threads/patch,
// each owns 16 output channels; effective weights shared across the patch's
// 4 pixels. f32x2 pixel-pair accumulators.
// Block = 256 threads = 128 patches x 2 halves. Grid = (2, 256, 8).
// ---------------------------------------------------------------------------
__global__ __launch_bounds__(256, 3)
void kernelA(const float* __restrict__ x,
             const float* __restrict__ mlp_w,
             const float* __restrict__ mlp_b,
             const float* __restrict__ conv_w,
             const float* __restrict__ conv_b)
{
    __shared__ __align__(16) u64 s_w1d[32][32];   // [c][o] = dup(conv_w[o, c])
    __shared__ __align__(16) u64 s_w2d[32][32];   // [c][o] = dup(conv_w[o, 32+c])
    __shared__ __align__(16) u64 s_bd[32];
    __shared__ float2 s_red[128][4];              // half-1 partial (mx, sum) per px

    const int tid = threadIdx.x;
    for (int i = tid; i < 1024; i += 256) {
        int o = i & 31, c = i >> 5;
        s_w1d[c][o] = dup2(conv_w[o * 64 + c]);
        s_w2d[c][o] = dup2(conv_w[o * 64 + 32 + c]);
    }
    if (tid < 32) s_bd[tid] = dup2(conv_b[tid]);
    __syncthreads();

    const int half = tid >> 7;
    const int pi   = tid & 127;
    const int wp   = blockIdx.x * 128 + pi;
    const int hp   = blockIdx.y;
    const int b    = blockIdx.z;

    const u64* __restrict__ x2 = (const u64*)x;
    const float mw  = __ldg(mlp_w);
    const float mb2 = 2.0f * __ldg(mlp_b);

    u64 acc[16][2];
#pragma unroll
    for (int k = 0; k < 16; k++) { acc[k][0] = 0ull; acc[k][1] = 0ull; }

#pragma unroll 8
    for (int c = 0; c < 32; c++) {
        unsigned p = (((unsigned)(b * 32 + c)) * 512u + 2u * hp) * 256u + wp;
        u64 r0 = x2[p];
        u64 r1 = x2[p + 256];
        float r0x, r0y, r1x, r1y;
        unpack2(r0, r0x, r0y);
        unpack2(r1, r1x, r1y);
        float m = fmaxf(fmaxf(r0x, r0y), fmaxf(r1x, r1y));
        float a = 0.25f * ((r0x + r0y) + (r1x + r1y));
        float g = fsigmoid(fmaf(m + a, mw, mb2));
        u64 gg = dup2(g);
        const ulonglong2* __restrict__ w1p = (const ulonglong2*)&s_w1d[c][half * 16];
        const ulonglong2* __restrict__ w2p = (const ulonglong2*)&s_w2d[c][half * 16];
#pragma unroll
        for (int k2 = 0; k2 < 8; k2++) {
            ulonglong2 a1 = w1p[k2];
            ulonglong2 a2 = w2p[k2];
            u64 we0 = fma2(gg, a1.x, a2.x);
            u64 we1 = fma2(gg, a1.y, a2.y);
            fma2acc(acc[2*k2  ][0], r0, we0);
            fma2acc(acc[2*k2  ][1], r1, we0);
            fma2acc(acc[2*k2+1][0], r0, we1);
            fma2acc(acc[2*k2+1][1], r1, we1);
        }
    }

#pragma unroll
    for (int k = 0; k < 16; k++) {
        u64 bk = s_bd[half * 16 + k];
        add2acc(acc[k][0], bk);
        add2acc(acc[k][1], bk);
    }

    float mx[4], sm[4];
#pragma unroll
    for (int j = 0; j < 4; j++) { mx[j] = -FLT_MAX; sm[j] = 0.f; }
#pragma unroll
    for (int k = 0; k < 16; k++) {
        float lo, hi;
        unpack2(acc[k][0], lo, hi);
        mx[0] = fmaxf(mx[0], lo); sm[0] += lo;
        mx[1] = fmaxf(mx[1], hi); sm[1] += hi;
        unpack2(acc[k][1], lo, hi);
        mx[2] = fmaxf(mx[2], lo); sm[2] += lo;
        mx[3] = fmaxf(mx[3], hi); sm[3] += hi;
    }
    if (half == 1) {
#pragma unroll
        for (int j = 0; j < 4; j++) s_red[pi][j] = make_float2(mx[j], sm[j]);
    }

    u64* __restrict__ fs2 = (u64*)g_fs;
#pragma unroll
    for (int k = 0; k < 16; k++) {
        int o = half * 16 + k;
        unsigned p = (((unsigned)(b * 32 + o)) * 512u + 2u * hp) * 256u + wp;
        fs2[p]       = acc[k][0];
        fs2[p + 256] = acc[k][1];
    }

    __syncthreads();
    if (half == 0) {
#pragma unroll
        for (int j = 0; j < 4; j++) {
            float2 r = s_red[pi][j];
            mx[j] = fmaxf(mx[j], r.x);
            sm[j] = (sm[j] + r.y) * (1.0f / 32.0f);
        }
        unsigned q = (((unsigned)b) * 512u + 2u * hp) * 256u + wp;
        ((float2*)g_cm)[q]       = make_float2(mx[0], mx[1]);
        ((float2*)g_cm)[q + 256] = make_float2(mx[2], mx[3]);
        ((float2*)g_ca)[q]       = make_float2(sm[0], sm[1]);
        ((float2*)g_ca)[q + 256] = make_float2(sm[2], sm[3]);
    }
}

// ---------------------------------------------------------------------------
// Kernel B (R12 best form): 7x7 SAME conv on [cm;ca] (2->32 ch), sigmoid,
// multiply by fs.
// Thread = 8 consecutive pixels (4 f32x2 pairs) x 4 output channels.
// Dual-parity swizzled smem tiles: all window loads native u64, conflict-free.
// dy fully unrolled -> immediate smem addressing. float4 epilogue.
// Block 256 = 8 channel-groups x 32 octets; tile 64w x 4h. Grid (8,128,8).
// ---------------------------------------------------------------------------
#define THB 4

__global__ __launch_bounds__(256, 3)
void kernelB(const float* __restrict__ cow,
             const float* __restrict__ cob,
             float* __restrict__ out)
{
    __shared__ __align__(16) float s_e[2][THB + 6][72];  // natural (swizzled)
    __shared__ __align__(16) float s_o[2][THB + 6][72];  // shifted by 1 (swizzled)
    __shared__ __align__(16) u64 s_wd[98][32];   // [tap][o] dup'd
    __shared__ __align__(16) u64 s_bd[32];

    const int tid = threadIdx.x;
    const int b   = blockIdx.z;
    const int tyb = blockIdx.y * THB;
    const int txb = blockIdx.x * 64;

    for (int i = tid; i < 98 * 32; i += 256) {
        int o = i / 98, tap = i - o * 98;
        float w = cow[i];
        s_wd[tap][o] = pack2(w, w);
    }
    if (tid < 32) s_bd[tid] = dup2(cob[tid]);

    for (int i = tid; i < 2 * (THB + 6) * 72; i += 256) {
        int plane = i / ((THB + 6) * 72);
        int rem   = i - plane * ((THB + 6) * 72);
        int r  = rem / 72;
        int cc = rem - r * 72;
        int h = tyb - 3 + r;
        int w = txb - 3 + cc;
        float v = 0.f;
        if (cc < 70 && h >= 0 && h < H_ && w >= 0 && w < W_)
            v = (plane ? g_ca : g_cm)[((unsigned)b * H_ + h) * W_ + w];
        s_e[plane][r][swzf(cc)] = v;
        if (cc >= 1) s_o[plane][r][swzf(cc - 1)] = v;
        if (cc == 71) s_o[plane][r][swzf(71)] = 0.f;
    }
    __syncthreads();

    const int cg  = tid >> 5;
    const int oct = tid & 31;
    const int ox  = oct & 7;
    const int oy  = oct >> 3;

    const int g0   = 2 * ox;
    const int offA = 4 * swzg(g0);
    const int offB = 4 * swzg(g0 + 1);
    const int offC = 4 * swzg(g0 + 2);
    const int offD = 4 * swzg(g0 + 3);

    u64 acc[4][4];
#pragma unroll
    for (int i = 0; i < 4; i++)
#pragma unroll
        for (int c = 0; c < 4; c++) acc[i][c] = s_bd[cg * 4 + c];

#pragma unroll 1
    for (int j = 0; j < 2; j++) {
        const float* __restrict__ base_e = &s_e[j][oy][0];
        const float* __restrict__ base_o = &s_o[j][oy][0];
#pragma unroll
        for (int dy = 0; dy < 7; dy++) {
            const float* __restrict__ rowe = base_e + dy * 72;
            const float* __restrict__ rowo = base_o + dy * 72;
            u64 pe[7], po[6];
            {
                ulonglong2 eA = *(const ulonglong2*)(rowe + offA);
                ulonglong2 eB = *(const ulonglong2*)(rowe + offB);
                ulonglong2 eC = *(const ulonglong2*)(rowe + offC);
                pe[0] = eA.x; pe[1] = eA.y;
                pe[2] = eB.x; pe[3] = eB.y;
                pe[4] = eC.x; pe[5] = eC.y;
                pe[6] = *(const u64*)(rowe + offD);
                ulonglong2 oA = *(const ulonglong2*)(rowo + offA);
                ulonglong2 oB = *(const ulonglong2*)(rowo + offB);
                po[0] = oA.x; po[1] = oA.y;
                po[2] = oB.x; po[3] = oB.y;
                po[4] = *(const u64*)(rowo + offC);
                po[5] = *(const u64*)(rowo + offC + 2);
            }

            const int tapbase = j * 49 + dy * 7;
#pragma unroll
            for (int dx = 0; dx < 7; dx++) {
                const ulonglong2* __restrict__ wp2 = (const ulonglong2*)&s_wd[tapbase + dx][cg * 4];
                ulonglong2 wa = wp2[0];
                ulonglong2 wb = wp2[1];
#pragma unroll
                for (int i = 0; i < 4; i++) {
                    u64 vv = (dx & 1) ? po[((dx - 1) >> 1) + i] : pe[(dx >> 1) + i];
                    fma2acc(acc[i][0], vv, wa.x);
                    fma2acc(acc[i][1], vv, wa.y);
                    fma2acc(acc[i][2], vv, wb.x);
                    fma2acc(acc[i][3], vv, wb.y);
                }
            }
        }
    }

    const int h  = tyb + oy;
    const int w0 = txb + ox * 8;
#pragma unroll
    for (int c = 0; c < 4; c++) {
        unsigned base = (((unsigned)(b * 32 + cg * 4 + c)) * 512u + h) * 512u + w0;
#pragma unroll
        for (int i2 = 0; i2 < 2; i2++) {
            float a0, a1, a2, a3;
            unpack2(acc[2*i2  ][c], a0, a1);
            unpack2(acc[2*i2+1][c], a2, a3);
            float4 f = *(const float4*)&g_fs[base + 4*i2];
            float4 r;
            r.x = fsigmoid(a0) * f.x;
            r.y = fsigmoid(a1) * f.y;
            r.z = fsigmoid(a2) * f.z;
            r.w = fsigmoid(a3) * f.w;
            *(float4*)&out[base + 4*i2] = r;
        }
    }
}

extern "C" void kernel_launch(void* const* d_in, const int* in_sizes, int n_in,
                              void* d_out, int out_size)
{
    (void)in_sizes; (void)n_in; (void)out_size;
    const float* x      = (const float*)d_in[0];
    const float* mlp_w  = (const float*)d_in[1];
    const float* mlp_b  = (const float*)d_in[2];
    const float* conv_w = (const float*)d_in[3];
    const float* conv_b = (const float*)d_in[4];
    const float* cow    = (const float*)d_in[5];
    const float* cob    = (const float*)d_in[6];
    float* out = (float*)d_out;

    kernelA<<<dim3(2, 256, 8), 256>>>(x, mlp_w, mlp_b, conv_w, conv_b);
    kernelB<<<dim3(8, 128, 8), 256>>>(cow, cob, out);
}

// round 16
// speedup vs baseline: 1.1056x; 1.1056x over previous
#include <cuda_runtime.h>
#include <float.h>
#include <math.h>

#define B_ 8
#define C_ 32
#define H_ 512
#define W_ 512
#define HW_ (H_*W_)

typedef unsigned long long u64;

// Scratch (allocation-free rule: static __device__ arrays)
__device__ float g_fs[B_*C_*H_*W_];   // conv1x1 output (pre-attention)
__device__ float g_cm[B_*H_*W_];      // channel max plane
__device__ float g_ca[B_*H_*W_];      // channel mean plane

__device__ __forceinline__ float fsigmoid(float z) {
    return 1.0f / (1.0f + __expf(-z));
}

// ---- packed f32x2 helpers (sm_10x) ----
__device__ __forceinline__ u64 pack2(float lo, float hi) {
    u64 r; asm("mov.b64 %0, {%1,%2};" : "=l"(r) : "f"(lo), "f"(hi)); return r;
}
__device__ __forceinline__ u64 dup2(float v) { return pack2(v, v); }
__device__ __forceinline__ void unpack2(u64 v, float &lo, float &hi) {
    asm("mov.b64 {%0,%1}, %2;" : "=f"(lo), "=f"(hi) : "l"(v));
}
__device__ __forceinline__ void fma2acc(u64 &acc, u64 a, u64 b) {
    asm("fma.rn.f32x2 %0, %1, %2, %0;" : "+l"(acc) : "l"(a), "l"(b));
}
__device__ __forceinline__ u64 fma2(u64 a, u64 b, u64 c) {
    u64 d; asm("fma.rn.f32x2 %0, %1, %2, %3;" : "=l"(d) : "l"(a), "l"(b), "l"(c)); return d;
}
__device__ __forceinline__ void add2acc(u64 &acc, u64 b) {
    asm("add.rn.f32x2 %0, %0, %1;" : "+l"(acc) : "l"(b));
}

// 4-float-group bank swizzle: flip group bit0 when group bit3 set.
__device__ __forceinline__ int swzg(int g) { return g ^ ((g >> 3) & 1); }
__device__ __forceinline__ int swzf(int cc) {
    int g = cc >> 2;
    return ((g ^ ((g >> 3) & 1)) << 2) | (cc & 3);
}

// ---------------------------------------------------------------------------
// Kernel A (two-pass): per 2x2 patch, 2 threads/patch, 16 output ch each.
// Pass 1: gates for all (c, patch) computed with deep LDG MLP, stored dup'd
// in smem. Pass 2: FMA mainloop; x re-reads hit L1, gate is one LDS —
// no MUFU/long-chain in the hot loop.
// Block = 256 threads = 128 patches x 2 halves. Grid = (2, 256, 8).
// ---------------------------------------------------------------------------
__global__ __launch_bounds__(256, 2)
void kernelA(const float* __restrict__ x,
             const float* __restrict__ mlp_w,
             const float* __restrict__ mlp_b,
             const float* __restrict__ conv_w,
             const float* __restrict__ conv_b)
{
    __shared__ __align__(16) u64 s_w1d[32][32];   // [c][o] = dup(conv_w[o, c])
    __shared__ __align__(16) u64 s_w2d[32][32];   // [c][o] = dup(conv_w[o, 32+c])
    __shared__ __align__(16) u64 s_bd[32];
    __shared__ __align__(16) u64 s_g[32][128];    // dup'd gate per (c, patch)
    __shared__ float2 s_red[128][4];              // half-1 partial (mx, sum) per px

    const int tid = threadIdx.x;
    for (int i = tid; i < 1024; i += 256) {
        int o = i & 31, c = i >> 5;
        s_w1d[c][o] = dup2(conv_w[o * 64 + c]);
        s_w2d[c][o] = dup2(conv_w[o * 64 + 32 + c]);
    }
    if (tid < 32) s_bd[tid] = dup2(conv_b[tid]);

    const int half = tid >> 7;
    const int pi   = tid & 127;
    const int wp   = blockIdx.x * 128 + pi;
    const int hp   = blockIdx.y;
    const int b    = blockIdx.z;

    const u64* __restrict__ x2 = (const u64*)x;
    const float mw  = __ldg(mlp_w);
    const float mb2 = 2.0f * __ldg(mlp_b);

    // ---- Pass 1: gates for this patch, channels [half*16, half*16+16) ----
    // 32 LDGs per thread issued with high MLP; MUFU chains independent.
    {
        const int c0 = half * 16;
#pragma unroll
        for (int cc = 0; cc < 16; cc++) {
            int c = c0 + cc;
            unsigned p = (((unsigned)(b * 32 + c)) * 512u + 2u * hp) * 256u + wp;
            u64 r0 = x2[p];
            u64 r1 = x2[p + 256];
            float r0x, r0y, r1x, r1y;
            unpack2(r0, r0x, r0y);
            unpack2(r1, r1x, r1y);
            float m = fmaxf(fmaxf(r0x, r0y), fmaxf(r1x, r1y));
            float a = 0.25f * ((r0x + r0y) + (r1x + r1y));
            float g = fsigmoid(fmaf(m + a, mw, mb2));
            s_g[c][pi] = dup2(g);
        }
    }
    __syncthreads();

    // ---- Pass 2: fused 1x1 conv; x hits L1, gate is one LDS ----
    u64 acc[16][2];
#pragma unroll
    for (int k = 0; k < 16; k++) { acc[k][0] = 0ull; acc[k][1] = 0ull; }

#pragma unroll 4
    for (int c = 0; c < 32; c++) {
        unsigned p = (((unsigned)(b * 32 + c)) * 512u + 2u * hp) * 256u + wp;
        u64 r0 = x2[p];          // L1 hit (loaded in pass 1 by this block)
        u64 r1 = x2[p + 256];
        u64 gg = s_g[c][pi];
        const ulonglong2* __restrict__ w1p = (const ulonglong2*)&s_w1d[c][half * 16];
        const ulonglong2* __restrict__ w2p = (const ulonglong2*)&s_w2d[c][half * 16];
#pragma unroll
        for (int k2 = 0; k2 < 8; k2++) {
            ulonglong2 a1 = w1p[k2];
            ulonglong2 a2 = w2p[k2];
            u64 we0 = fma2(gg, a1.x, a2.x);
            u64 we1 = fma2(gg, a1.y, a2.y);
            fma2acc(acc[2*k2  ][0], r0, we0);
            fma2acc(acc[2*k2  ][1], r1, we0);
            fma2acc(acc[2*k2+1][0], r0, we1);
            fma2acc(acc[2*k2+1][1], r1, we1);
        }
    }

#pragma unroll
    for (int k = 0; k < 16; k++) {
        u64 bk = s_bd[half * 16 + k];
        add2acc(acc[k][0], bk);
        add2acc(acc[k][1], bk);
    }

    float mx[4], sm[4];
#pragma unroll
    for (int j = 0; j < 4; j++) { mx[j] = -FLT_MAX; sm[j] = 0.f; }
#pragma unroll
    for (int k = 0; k < 16; k++) {
        float lo, hi;
        unpack2(acc[k][0], lo, hi);
        mx[0] = fmaxf(mx[0], lo); sm[0] += lo;
        mx[1] = fmaxf(mx[1], hi); sm[1] += hi;
        unpack2(acc[k][1], lo, hi);
        mx[2] = fmaxf(mx[2], lo); sm[2] += lo;
        mx[3] = fmaxf(mx[3], hi); sm[3] += hi;
    }
    if (half == 1) {
#pragma unroll
        for (int j = 0; j < 4; j++) s_red[pi][j] = make_float2(mx[j], sm[j]);
    }

    u64* __restrict__ fs2 = (u64*)g_fs;
#pragma unroll
    for (int k = 0; k < 16; k++) {
        int o = half * 16 + k;
        unsigned p = (((unsigned)(b * 32 + o)) * 512u + 2u * hp) * 256u + wp;
        fs2[p]       = acc[k][0];
        fs2[p + 256] = acc[k][1];
    }

    __syncthreads();
    if (half == 0) {
#pragma unroll
        for (int j = 0; j < 4; j++) {
            float2 r = s_red[pi][j];
            mx[j] = fmaxf(mx[j], r.x);
            sm[j] = (sm[j] + r.y) * (1.0f / 32.0f);
        }
        unsigned q = (((unsigned)b) * 512u + 2u * hp) * 256u + wp;
        ((float2*)g_cm)[q]       = make_float2(mx[0], mx[1]);
        ((float2*)g_cm)[q + 256] = make_float2(mx[2], mx[3]);
        ((float2*)g_ca)[q]       = make_float2(sm[0], sm[1]);
        ((float2*)g_ca)[q + 256] = make_float2(sm[2], sm[3]);
    }
}

// ---------------------------------------------------------------------------
// Kernel B (R12 best form): 7x7 SAME conv on [cm;ca] (2->32 ch), sigmoid,
// multiply by fs.
// Thread = 8 consecutive pixels (4 f32x2 pairs) x 4 output channels.
// Dual-parity swizzled smem tiles: all window loads native u64, conflict-free.
// dy fully unrolled -> immediate smem addressing. float4 epilogue.
// Block 256 = 8 channel-groups x 32 octets; tile 64w x 4h. Grid (8,128,8).
// ---------------------------------------------------------------------------
#define THB 4

__global__ __launch_bounds__(256, 3)
void kernelB(const float* __restrict__ cow,
             const float* __restrict__ cob,
             float* __restrict__ out)
{
    __shared__ __align__(16) float s_e[2][THB + 6][72];  // natural (swizzled)
    __shared__ __align__(16) float s_o[2][THB + 6][72];  // shifted by 1 (swizzled)
    __shared__ __align__(16) u64 s_wd[98][32];   // [tap][o] dup'd
    __shared__ __align__(16) u64 s_bd[32];

    const int tid = threadIdx.x;
    const int b   = blockIdx.z;
    const int tyb = blockIdx.y * THB;
    const int txb = blockIdx.x * 64;

    for (int i = tid; i < 98 * 32; i += 256) {
        int o = i / 98, tap = i - o * 98;
        float w = cow[i];
        s_wd[tap][o] = pack2(w, w);
    }
    if (tid < 32) s_bd[tid] = dup2(cob[tid]);

    for (int i = tid; i < 2 * (THB + 6) * 72; i += 256) {
        int plane = i / ((THB + 6) * 72);
        int rem   = i - plane * ((THB + 6) * 72);
        int r  = rem / 72;
        int cc = rem - r * 72;
        int h = tyb - 3 + r;
        int w = txb - 3 + cc;
        float v = 0.f;
        if (cc < 70 && h >= 0 && h < H_ && w >= 0 && w < W_)
            v = (plane ? g_ca : g_cm)[((unsigned)b * H_ + h) * W_ + w];
        s_e[plane][r][swzf(cc)] = v;
        if (cc >= 1) s_o[plane][r][swzf(cc - 1)] = v;
        if (cc == 71) s_o[plane][r][swzf(71)] = 0.f;
    }
    __syncthreads();

    const int cg  = tid >> 5;
    const int oct = tid & 31;
    const int ox  = oct & 7;
    const int oy  = oct >> 3;

    const int g0   = 2 * ox;
    const int offA = 4 * swzg(g0);
    const int offB = 4 * swzg(g0 + 1);
    const int offC = 4 * swzg(g0 + 2);
    const int offD = 4 * swzg(g0 + 3);

    u64 acc[4][4];
#pragma unroll
    for (int i = 0; i < 4; i++)
#pragma unroll
        for (int c = 0; c < 4; c++) acc[i][c] = s_bd[cg * 4 + c];

#pragma unroll 1
    for (int j = 0; j < 2; j++) {
        const float* __restrict__ base_e = &s_e[j][oy][0];
        const float* __restrict__ base_o = &s_o[j][oy][0];
#pragma unroll
        for (int dy = 0; dy < 7; dy++) {
            const float* __restrict__ rowe = base_e + dy * 72;
            const float* __restrict__ rowo = base_o + dy * 72;
            u64 pe[7], po[6];
            {
                ulonglong2 eA = *(const ulonglong2*)(rowe + offA);
                ulonglong2 eB = *(const ulonglong2*)(rowe + offB);
                ulonglong2 eC = *(const ulonglong2*)(rowe + offC);
                pe[0] = eA.x; pe[1] = eA.y;
                pe[2] = eB.x; pe[3] = eB.y;
                pe[4] = eC.x; pe[5] = eC.y;
                pe[6] = *(const u64*)(rowe + offD);
                ulonglong2 oA = *(const ulonglong2*)(rowo + offA);
                ulonglong2 oB = *(const ulonglong2*)(rowo + offB);
                po[0] = oA.x; po[1] = oA.y;
                po[2] = oB.x; po[3] = oB.y;
                po[4] = *(const u64*)(rowo + offC);
                po[5] = *(const u64*)(rowo + offC + 2);
            }

            const int tapbase = j * 49 + dy * 7;
#pragma unroll
            for (int dx = 0; dx < 7; dx++) {
                const ulonglong2* __restrict__ wp2 = (const ulonglong2*)&s_wd[tapbase + dx][cg * 4];
                ulonglong2 wa = wp2[0];
                ulonglong2 wb = wp2[1];
#pragma unroll
                for (int i = 0; i < 4; i++) {
                    u64 vv = (dx & 1) ? po[((dx - 1) >> 1) + i] : pe[(dx >> 1) + i];
                    fma2acc(acc[i][0], vv, wa.x);
                    fma2acc(acc[i][1], vv, wa.y);
                    fma2acc(acc[i][2], vv, wb.x);
                    fma2acc(acc[i][3], vv, wb.y);
                }
            }
        }
    }

    const int h  = tyb + oy;
    const int w0 = txb + ox * 8;
#pragma unroll
    for (int c = 0; c < 4; c++) {
        unsigned base = (((unsigned)(b * 32 + cg * 4 + c)) * 512u + h) * 512u + w0;
#pragma unroll
        for (int i2 = 0; i2 < 2; i2++) {
            float a0, a1, a2, a3;
            unpack2(acc[2*i2  ][c], a0, a1);
            unpack2(acc[2*i2+1][c], a2, a3);
            float4 f = *(const float4*)&g_fs[base + 4*i2];
            float4 r;
            r.x = fsigmoid(a0) * f.x;
            r.y = fsigmoid(a1) * f.y;
            r.z = fsigmoid(a2) * f.z;
            r.w = fsigmoid(a3) * f.w;
            *(float4*)&out[base + 4*i2] = r;
        }
    }
}

extern "C" void kernel_launch(void* const* d_in, const int* in_sizes, int n_in,
                              void* d_out, int out_size)
{
    (void)in_sizes; (void)n_in; (void)out_size;
    const float* x      = (const float*)d_in[0];
    const float* mlp_w  = (const float*)d_in[1];
    const float* mlp_b  = (const float*)d_in[2];
    const float* conv_w = (const float*)d_in[3];
    const float* conv_b = (const float*)d_in[4];
    const float* cow    = (const float*)d_in[5];
    const float* cob    = (const float*)d_in[6];
    float* out = (float*)d_out;

    kernelA<<<dim3(2, 256, 8), 256>>>(x, mlp_w, mlp_b, conv_w, conv_b);
    kernelB<<<dim3(8, 128, 8), 256>>>(cow, cob, out);
}